// round 2
// baseline (speedup 1.0000x reference)
#include <cuda_runtime.h>

#define Bv   16
#define Nv   5000
#define Ev   160000
#define Cv   64
#define BNv  80000
#define BEv  2560000
#define ETOTv 2640000
#define OUT_MAIN 5120000   // BNv * Cv

// ---------------- scratch (static __device__, no allocs) ----------------
__device__ float g_xlS[Nv * Cv];     // xl for nodes < 5000 (message sources)
__device__ float g_aS[Nv];
__device__ float g_aD[Nv];
__device__ int   g_cnt[Nv];
__device__ int   g_off[Nv + 1];
__device__ int   g_cur[Nv];
__device__ int   g_bucket[Ev];
__device__ float g_alphaP[Ev];       // unnormalized exp(alpha - amax) per unique edge
__device__ float g_rdenom[Nv];
__device__ float g_selfNorm[Nv];
__device__ float g_part[512];
__device__ float g_c;                // sum_k W_edge[k]*att_edge[k]
__device__ float g_meanC;            // mean(edge_attr) * c

// ---------------- small utility kernels ----------------
__global__ void k_zero() {
    int i = blockIdx.x * blockDim.x + threadIdx.x;
    if (i < Nv) g_cnt[i] = 0;
}

__global__ void k_hist(const int* __restrict__ ei) {
    int e = blockIdx.x * blockDim.x + threadIdx.x;
    if (e < Ev) atomicAdd(&g_cnt[ei[Ev + e]], 1);   // row 1 = dst
}

__global__ void k_red1(const float* __restrict__ ea) {
    __shared__ float sh[256];
    float s = 0.f;
    for (int i = blockIdx.x * 256 + threadIdx.x; i < Ev; i += 512 * 256) s += ea[i];
    sh[threadIdx.x] = s; __syncthreads();
    for (int o = 128; o > 0; o >>= 1) {
        if (threadIdx.x < o) sh[threadIdx.x] += sh[threadIdx.x + o];
        __syncthreads();
    }
    if (threadIdx.x == 0) g_part[blockIdx.x] = sh[0];
}

__global__ void k_red2(const float* __restrict__ W_edge, const float* __restrict__ att_edge) {
    __shared__ float sh[512];
    int t = threadIdx.x;
    sh[t] = g_part[t]; __syncthreads();
    for (int o = 256; o > 0; o >>= 1) {
        if (t < o) sh[t] += sh[t + o];
        __syncthreads();
    }
    float sumEA = sh[0];
    __syncthreads();
    sh[t] = (t < Cv) ? W_edge[t] * att_edge[t] : 0.f;
    __syncthreads();
    for (int o = 256; o > 0; o >>= 1) {
        if (t < o) sh[t] += sh[t + o];
        __syncthreads();
    }
    if (t == 0) {
        float c = sh[0];
        g_c = c;
        g_meanC = (sumEA / (float)Ev) * c;   // mean over tiled == mean over E
    }
}

__global__ void k_scan() {   // 1 block, 1024 threads, 5 elems each
    __shared__ int sh[1024];
    int t = threadIdx.x;
    int v[5]; int sum = 0;
#pragma unroll
    for (int j = 0; j < 5; j++) {
        int i = t * 5 + j;
        v[j] = (i < Nv) ? g_cnt[i] : 0;
        sum += v[j];
    }
    sh[t] = sum; __syncthreads();
    for (int d = 1; d < 1024; d <<= 1) {
        int val = (t >= d) ? sh[t - d] : 0;
        __syncthreads();
        sh[t] += val;
        __syncthreads();
    }
    int run = sh[t] - sum;   // exclusive prefix
#pragma unroll
    for (int j = 0; j < 5; j++) {
        int i = t * 5 + j;
        if (i < Nv) { g_off[i] = run; g_cur[i] = run; run += v[j]; }
    }
    if (t == 1023) g_off[Nv] = sh[1023];
}

__global__ void k_scatter(const int* __restrict__ ei) {
    int e = blockIdx.x * blockDim.x + threadIdx.x;
    if (e < Ev) {
        int d = ei[Ev + e];
        int p = atomicAdd(&g_cur[d], 1);
        g_bucket[p] = e;
    }
}

// ---------------- dense transform: xl = x @ W^T (+bias into out) ----------------
__global__ void __launch_bounds__(256) k_gemm(const float* __restrict__ x,
                                              const float* __restrict__ W,
                                              const float* __restrict__ bias,
                                              float* __restrict__ out) {
    __shared__ float Xs[64 * 65];   // Xs[k][r] = x[nb+r][k]
    __shared__ float Ws[64 * 65];   // Ws[k][o] = W[o][k]
    int tid = threadIdx.x;
    int nb = blockIdx.x * 64;
#pragma unroll
    for (int it = 0; it < 4; it++) {
        int fl = tid + it * 256;
        int row = fl >> 4;
        int q = fl & 15;
        float4 v = *(const float4*)(x + (long long)(nb + row) * 64 + q * 4);
        Xs[(4 * q + 0) * 65 + row] = v.x;
        Xs[(4 * q + 1) * 65 + row] = v.y;
        Xs[(4 * q + 2) * 65 + row] = v.z;
        Xs[(4 * q + 3) * 65 + row] = v.w;
        float4 w = *(const float4*)(W + row * 64 + q * 4);
        Ws[(4 * q + 0) * 65 + row] = w.x;
        Ws[(4 * q + 1) * 65 + row] = w.y;
        Ws[(4 * q + 2) * 65 + row] = w.z;
        Ws[(4 * q + 3) * 65 + row] = w.w;
    }
    __syncthreads();
    int tx = tid & 15, ty = tid >> 4;
    int r0 = ty * 4, c0 = tx * 4;
    float acc[4][4] = {};
#pragma unroll 8
    for (int k = 0; k < 64; k++) {
        float a0 = Xs[k * 65 + r0 + 0];
        float a1 = Xs[k * 65 + r0 + 1];
        float a2 = Xs[k * 65 + r0 + 2];
        float a3 = Xs[k * 65 + r0 + 3];
        float b0 = Ws[k * 65 + c0 + 0];
        float b1 = Ws[k * 65 + c0 + 1];
        float b2 = Ws[k * 65 + c0 + 2];
        float b3 = Ws[k * 65 + c0 + 3];
        acc[0][0] += a0 * b0; acc[0][1] += a0 * b1; acc[0][2] += a0 * b2; acc[0][3] += a0 * b3;
        acc[1][0] += a1 * b0; acc[1][1] += a1 * b1; acc[1][2] += a1 * b2; acc[1][3] += a1 * b3;
        acc[2][0] += a2 * b0; acc[2][1] += a2 * b1; acc[2][2] += a2 * b2; acc[2][3] += a2 * b3;
        acc[3][0] += a3 * b0; acc[3][1] += a3 * b1; acc[3][2] += a3 * b2; acc[3][3] += a3 * b3;
    }
    float4 bb = *(const float4*)(bias + c0);
#pragma unroll
    for (int i = 0; i < 4; i++) {
        int n = nb + r0 + i;
        float4 o;
        o.x = acc[i][0] + bb.x; o.y = acc[i][1] + bb.y;
        o.z = acc[i][2] + bb.z; o.w = acc[i][3] + bb.w;
        *(float4*)(out + (long long)n * 64 + c0) = o;
        if (n < Nv) {
            float4 xo;
            xo.x = acc[i][0]; xo.y = acc[i][1]; xo.z = acc[i][2]; xo.w = acc[i][3];
            *(float4*)(&g_xlS[n * 64 + c0]) = xo;
        }
    }
}

// ---------------- per-node attention scalars (nodes < 5000 only) ----------------
__global__ void k_attn(const float* __restrict__ attS, const float* __restrict__ attD) {
    int w = (blockIdx.x * blockDim.x + threadIdx.x) >> 5;   // one warp per node
    int lane = threadIdx.x & 31;
    if (w >= Nv) return;
    float2 v = *(const float2*)(g_xlS + w * 64 + lane * 2);
    float2 a = *(const float2*)(attS + lane * 2);
    float2 b = *(const float2*)(attD + lane * 2);
    float s = v.x * a.x + v.y * a.y;
    float d = v.x * b.x + v.y * b.y;
#pragma unroll
    for (int o = 16; o; o >>= 1) {
        s += __shfl_xor_sync(0xffffffffu, s, o);
        d += __shfl_xor_sync(0xffffffffu, d, o);
    }
    if (lane == 0) { g_aS[w] = s; g_aD[w] = d; }
}

// ---------------- per-destination softmax + aggregation ----------------
__global__ void __launch_bounds__(64) k_dst(const int* __restrict__ ei,
                                            const float* __restrict__ ea,
                                            const float* __restrict__ bias,
                                            float* __restrict__ out) {
    int d = blockIdx.x;
    int t = threadIdx.x;        // 64 threads = 64 channels
    int s0 = g_off[d], s1 = g_off[d + 1];
    float c = g_c;
    float aDd = g_aD[d];
    float selfRaw;
    {
        float x = g_aS[d] + aDd + g_meanC;
        selfRaw = x > 0.f ? x : 0.2f * x;
    }
    // pass 1: segment max (self-loop included)
    float mx = selfRaw;
    for (int j = s0 + t; j < s1; j += 64) {
        int e = g_bucket[j];
        float x = g_aS[ei[e]] + aDd + ea[e] * c;
        x = x > 0.f ? x : 0.2f * x;
        mx = fmaxf(mx, x);
    }
    __shared__ float red[64];
    red[t] = mx; __syncthreads();
    for (int o = 32; o; o >>= 1) {
        if (t < o) red[t] = fmaxf(red[t], red[t + o]);
        __syncthreads();
    }
    float amax = red[0];
    __syncthreads();
    // pass 2: exp + channel accumulation (chunked by 64)
    __shared__ float sP[64];
    __shared__ int   sS[64];
    float acc = 0.f;
    float psum = 0.f;
    for (int base = s0; base < s1; base += 64) {
        int m = s1 - base; if (m > 64) m = 64;
        if (t < m) {
            int e = g_bucket[base + t];
            int s = ei[e];
            float x = g_aS[s] + aDd + ea[e] * c;
            x = x > 0.f ? x : 0.2f * x;
            float p = expf(x - amax);
            sP[t] = p; sS[t] = s;
            psum += p;
            g_alphaP[e] = p;
        }
        __syncthreads();
        for (int j = 0; j < m; j++)
            acc += sP[j] * g_xlS[sS[j] * 64 + t];
        __syncthreads();
    }
    red[t] = psum; __syncthreads();
    for (int o = 32; o; o >>= 1) {
        if (t < o) red[t] += red[t + o];
        __syncthreads();
    }
    float sumP = red[0];
    float pSelf = expf(selfRaw - amax);
    float denom = (float)Bv * sumP + pSelf;
    float rd = 1.f / (denom + 1e-16f);
    out[(long long)d * 64 + t] = ((float)Bv * acc + pSelf * g_xlS[d * 64 + t]) * rd + bias[t];
    if (t == 0) { g_rdenom[d] = rd; g_selfNorm[d] = pSelf * rd; }
}

// ---------------- tuple tail: [src row | dst row | alpha tiled | alpha self] ----------------
__global__ void k_tail(const int* __restrict__ ei, float* __restrict__ outTail, long long total) {
    long long idx = blockIdx.x * (long long)blockDim.x + threadIdx.x;
    long long stride = gridDim.x * (long long)blockDim.x;
    for (; idx < total; idx += stride) {
        long long i = idx;
        float val;
        if (i < (long long)ETOTv) {                       // src row
            long long k = i;
            val = (k < (long long)BEv) ? (float)ei[(int)(k % Ev)] : (float)(k - BEv);
        } else if (i < 2LL * ETOTv) {                     // dst row
            long long k = i - ETOTv;
            val = (k < (long long)BEv) ? (float)ei[Ev + (int)(k % Ev)] : (float)(k - BEv);
        } else if (i < 2LL * ETOTv + BEv) {               // alpha for tiled edges
            int e = (int)((i - 2LL * ETOTv) % Ev);
            val = g_alphaP[e] * g_rdenom[ei[Ev + e]];
        } else if (i < 2LL * ETOTv + BEv + BNv) {         // alpha for self-loops
            int d = (int)(i - (2LL * ETOTv + (long long)BEv));
            val = (d < Nv) ? g_selfNorm[d] : 1.0f;
        } else {
            val = 0.f;
        }
        outTail[idx] = val;
    }
}

// ---------------- launch ----------------
extern "C" void kernel_launch(void* const* d_in, const int* in_sizes, int n_in,
                              void* d_out, int out_size) {
    const float* data   = (const float*)d_in[0];
    const int*   ei     = (const int*)  d_in[1];
    const float* ea     = (const float*)d_in[2];
    const float* W      = (const float*)d_in[3];
    const float* W_edge = (const float*)d_in[4];
    const float* attS   = (const float*)d_in[5];
    const float* attD   = (const float*)d_in[6];
    const float* attE   = (const float*)d_in[7];
    const float* bias   = (const float*)d_in[8];
    float* out = (float*)d_out;

    k_zero<<<(Nv + 255) / 256, 256>>>();
    k_hist<<<(Ev + 255) / 256, 256>>>(ei);
    k_red1<<<512, 256>>>(ea);
    k_red2<<<1, 512>>>(W_edge, attE);
    k_scan<<<1, 1024>>>();
    k_scatter<<<(Ev + 255) / 256, 256>>>(ei);
    k_gemm<<<BNv / 64, 256>>>(data, W, bias, out);
    k_attn<<<(Nv * 32 + 255) / 256, 256>>>(attS, attD);
    k_dst<<<Nv, 64>>>(ei, ea, bias, out);

    if (out_size > OUT_MAIN) {
        long long total = (long long)out_size - OUT_MAIN;
        long long g = (total + 255) / 256;
        if (g > 65535LL * 4) g = 65535LL * 4;
        k_tail<<<(int)g, 256>>>(ei, out + OUT_MAIN, total);
    }
}

// round 3
// speedup vs baseline: 1.1336x; 1.1336x over previous
#include <cuda_runtime.h>

#define Bv   16
#define Nv   5000
#define Ev   160000
#define Cv   64
#define BNv  80000
#define BEv  2560000
#define ETOTv 2640000
#define OUT_MAIN 5120000   // BNv * Cv
#define NPART 625          // Ev / 256

// ---------------- scratch (static __device__, no allocs) ----------------
__device__ float g_xlS[Nv * Cv];     // xl for nodes < 5000 (message sources)
__device__ float g_aS[Nv];
__device__ float g_aD[Nv];
__device__ int   g_cnt[Nv];
__device__ int   g_off[Nv + 1];
__device__ int   g_cur[Nv];
__device__ int   g_bucket[Ev];
__device__ float g_alphaP[Ev];       // unnormalized exp(alpha) per unique edge
__device__ float g_rdenom[Nv];
__device__ float g_selfNorm[Nv];
__device__ float g_part[NPART];
__device__ float g_c;                // sum_k W_edge[k]*att_edge[k]
__device__ float g_meanC;            // mean(edge_attr) * c

// ---------------- fused histogram + edge_attr partial sums ----------------
__global__ void k_histred(const int* __restrict__ ei, const float* __restrict__ ea) {
    __shared__ float sh[256];
    int e = blockIdx.x * 256 + threadIdx.x;          // exact: Ev = 625*256
    atomicAdd(&g_cnt[ei[Ev + e]], 1);                // row 1 = dst
    sh[threadIdx.x] = ea[e];
    __syncthreads();
#pragma unroll
    for (int o = 128; o > 0; o >>= 1) {
        if (threadIdx.x < o) sh[threadIdx.x] += sh[threadIdx.x + o];
        __syncthreads();
    }
    if (threadIdx.x == 0) g_part[blockIdx.x] = sh[0];
}

// ---------------- fused: reduce partials + compute c + exclusive scan ----------------
__global__ void k_scanred(const float* __restrict__ W_edge, const float* __restrict__ att_edge) {
    __shared__ float fsh[1024];
    __shared__ int   sh[1024];
    __shared__ float cbox[2];
    int t = threadIdx.x;

    // phase A1: sum of ea partials
    fsh[t] = (t < NPART) ? g_part[t] : 0.f;
    __syncthreads();
#pragma unroll
    for (int o = 512; o > 0; o >>= 1) {
        if (t < o) fsh[t] += fsh[t + o];
        __syncthreads();
    }
    if (t == 0) cbox[0] = fsh[0];
    __syncthreads();
    // phase A2: c = sum W_edge * att_edge
    fsh[t] = (t < Cv) ? W_edge[t] * att_edge[t] : 0.f;
    __syncthreads();
#pragma unroll
    for (int o = 512; o > 0; o >>= 1) {
        if (t < o) fsh[t] += fsh[t + o];
        __syncthreads();
    }
    if (t == 0) {
        float c = fsh[0];
        g_c = c;
        g_meanC = (cbox[0] / (float)Ev) * c;
    }

    // phase B: exclusive scan of g_cnt (5 per thread)
    int v[5]; int sum = 0;
#pragma unroll
    for (int j = 0; j < 5; j++) {
        int i = t * 5 + j;
        v[j] = (i < Nv) ? g_cnt[i] : 0;
        sum += v[j];
    }
    sh[t] = sum; __syncthreads();
    for (int d = 1; d < 1024; d <<= 1) {
        int val = (t >= d) ? sh[t - d] : 0;
        __syncthreads();
        sh[t] += val;
        __syncthreads();
    }
    int run = sh[t] - sum;   // exclusive prefix
#pragma unroll
    for (int j = 0; j < 5; j++) {
        int i = t * 5 + j;
        if (i < Nv) { g_off[i] = run; g_cur[i] = run; run += v[j]; }
    }
    if (t == 1023) g_off[Nv] = sh[1023];
}

__global__ void k_scatter(const int* __restrict__ ei) {
    int e = blockIdx.x * 256 + threadIdx.x;          // exact grid
    int d = ei[Ev + e];
    int p = atomicAdd(&g_cur[d], 1);
    g_bucket[p] = e;
}

// ---- dense transform: xl = x @ W^T (+bias into out) + fused attn dots ----
__global__ void __launch_bounds__(256) k_gemm(const float* __restrict__ x,
                                              const float* __restrict__ W,
                                              const float* __restrict__ bias,
                                              const float* __restrict__ attS,
                                              const float* __restrict__ attD,
                                              float* __restrict__ out) {
    __shared__ float Xs[64 * 68];   // Xs[k][r] = x[nb+r][k], pad 68 (16B-aligned rows)
    __shared__ float Ws[64 * 68];   // Ws[k][o] = W[o][k]
    int tid = threadIdx.x;
    int nb = blockIdx.x * 64;
#pragma unroll
    for (int it = 0; it < 4; it++) {
        int fl = tid + it * 256;
        int row = fl >> 4;
        int q = fl & 15;
        float4 v = *(const float4*)(x + (long long)(nb + row) * 64 + q * 4);
        Xs[(4 * q + 0) * 68 + row] = v.x;
        Xs[(4 * q + 1) * 68 + row] = v.y;
        Xs[(4 * q + 2) * 68 + row] = v.z;
        Xs[(4 * q + 3) * 68 + row] = v.w;
        float4 w = *(const float4*)(W + row * 64 + q * 4);
        Ws[(4 * q + 0) * 68 + row] = w.x;
        Ws[(4 * q + 1) * 68 + row] = w.y;
        Ws[(4 * q + 2) * 68 + row] = w.z;
        Ws[(4 * q + 3) * 68 + row] = w.w;
    }
    __syncthreads();
    int tx = tid & 15, ty = tid >> 4;
    int r0 = ty * 4, c0 = tx * 4;
    float acc[4][4] = {};
#pragma unroll 8
    for (int k = 0; k < 64; k++) {
        float4 a = *(const float4*)(Xs + k * 68 + r0);
        float4 b = *(const float4*)(Ws + k * 68 + c0);
        acc[0][0] += a.x * b.x; acc[0][1] += a.x * b.y; acc[0][2] += a.x * b.z; acc[0][3] += a.x * b.w;
        acc[1][0] += a.y * b.x; acc[1][1] += a.y * b.y; acc[1][2] += a.y * b.z; acc[1][3] += a.y * b.w;
        acc[2][0] += a.z * b.x; acc[2][1] += a.z * b.y; acc[2][2] += a.z * b.z; acc[2][3] += a.z * b.w;
        acc[3][0] += a.w * b.x; acc[3][1] += a.w * b.y; acc[3][2] += a.w * b.z; acc[3][3] += a.w * b.w;
    }
    float4 bb = *(const float4*)(bias + c0);
#pragma unroll
    for (int i = 0; i < 4; i++) {
        int n = nb + r0 + i;
        float4 o;
        o.x = acc[i][0] + bb.x; o.y = acc[i][1] + bb.y;
        o.z = acc[i][2] + bb.z; o.w = acc[i][3] + bb.w;
        *(float4*)(out + (long long)n * 64 + c0) = o;
        if (n < Nv) {
            float4 xo;
            xo.x = acc[i][0]; xo.y = acc[i][1]; xo.z = acc[i][2]; xo.w = acc[i][3];
            *(float4*)(&g_xlS[n * 64 + c0]) = xo;
        }
    }
    // fused attention dots for source nodes (< Nv): rows only exist in blocks nb < Nv
    if (nb < Nv) {
        float4 as4 = *(const float4*)(attS + c0);
        float4 ad4 = *(const float4*)(attD + c0);
        float ps[4], pd[4];
#pragma unroll
        for (int i = 0; i < 4; i++) {
            ps[i] = acc[i][0] * as4.x + acc[i][1] * as4.y + acc[i][2] * as4.z + acc[i][3] * as4.w;
            pd[i] = acc[i][0] * ad4.x + acc[i][1] * ad4.y + acc[i][2] * ad4.z + acc[i][3] * ad4.w;
        }
#pragma unroll
        for (int o = 8; o > 0; o >>= 1) {
#pragma unroll
            for (int i = 0; i < 4; i++) {
                ps[i] += __shfl_xor_sync(0xffffffffu, ps[i], o);
                pd[i] += __shfl_xor_sync(0xffffffffu, pd[i], o);
            }
        }
        if (tx == 0) {
#pragma unroll
            for (int i = 0; i < 4; i++) {
                int n = nb + r0 + i;
                if (n < Nv) { g_aS[n] = ps[i]; g_aD[n] = pd[i]; }
            }
        }
    }
}

// ---------------- per-destination softmax + aggregation (single pass, no amax) ----------------
__global__ void __launch_bounds__(64) k_dst(const int* __restrict__ ei,
                                            const float* __restrict__ ea,
                                            const float* __restrict__ bias,
                                            float* __restrict__ out) {
    int d = blockIdx.x;
    int t = threadIdx.x;        // 64 threads = 64 channels
    int s0 = g_off[d], s1 = g_off[d + 1];
    float c = g_c;
    float aDd = g_aD[d];
    float pSelf;
    {
        float x = g_aS[d] + aDd + g_meanC;
        x = x > 0.f ? x : 0.2f * x;
        pSelf = __expf(x);
    }
    __shared__ float sP[64];
    __shared__ int   sS[64];
    __shared__ float red[64];
    float acc = 0.f;
    float psum = 0.f;
    for (int base = s0; base < s1; base += 64) {
        int m = s1 - base; if (m > 64) m = 64;
        if (t < m) {
            int e = g_bucket[base + t];
            int s = ei[e];
            float x = g_aS[s] + aDd + ea[e] * c;
            x = x > 0.f ? x : 0.2f * x;
            float p = __expf(x);
            sP[t] = p; sS[t] = s;
            psum += p;
            g_alphaP[e] = p;
        }
        __syncthreads();
        for (int j = 0; j < m; j++)
            acc += sP[j] * g_xlS[sS[j] * 64 + t];
        __syncthreads();
    }
    red[t] = psum; __syncthreads();
#pragma unroll
    for (int o = 32; o > 0; o >>= 1) {
        if (t < o) red[t] += red[t + o];
        __syncthreads();
    }
    float sumP = red[0];
    float denom = (float)Bv * sumP + pSelf;
    float rd = 1.f / (denom + 1e-16f);
    out[(long long)d * 64 + t] = ((float)Bv * acc + pSelf * g_xlS[d * 64 + t]) * rd + bias[t];
    if (t == 0) { g_rdenom[d] = rd; g_selfNorm[d] = pSelf * rd; }
}

// ---------------- tuple tail: [src row | dst row | alpha tiled | alpha self] ----------------
__global__ void k_tail(const int* __restrict__ ei, float* __restrict__ outTail, int total) {
    int i = blockIdx.x * 256 + threadIdx.x;
    if (i >= total) return;
    float val;
    if (i < ETOTv) {                                  // src row
        val = (i < BEv) ? (float)ei[i - (i / Ev) * Ev] : (float)(i - BEv);
    } else if (i < 2 * ETOTv) {                       // dst row
        int k = i - ETOTv;
        val = (k < BEv) ? (float)ei[Ev + (k - (k / Ev) * Ev)] : (float)(k - BEv);
    } else if (i < 2 * ETOTv + BEv) {                 // alpha for tiled edges
        int k = i - 2 * ETOTv;
        int e = k - (k / Ev) * Ev;
        val = g_alphaP[e] * g_rdenom[ei[Ev + e]];
    } else if (i < 2 * ETOTv + BEv + BNv) {           // alpha for self-loops
        int d = i - (2 * ETOTv + BEv);
        val = (d < Nv) ? g_selfNorm[d] : 1.0f;
    } else {
        val = 0.f;
    }
    outTail[i] = val;
}

// ---------------- launch ----------------
extern "C" void kernel_launch(void* const* d_in, const int* in_sizes, int n_in,
                              void* d_out, int out_size) {
    const float* data   = (const float*)d_in[0];
    const int*   ei     = (const int*)  d_in[1];
    const float* ea     = (const float*)d_in[2];
    const float* W      = (const float*)d_in[3];
    const float* W_edge = (const float*)d_in[4];
    const float* attS   = (const float*)d_in[5];
    const float* attD   = (const float*)d_in[6];
    const float* attE   = (const float*)d_in[7];
    const float* bias   = (const float*)d_in[8];
    float* out = (float*)d_out;

    void* cntAddr = nullptr;
    cudaGetSymbolAddress(&cntAddr, g_cnt);
    cudaMemsetAsync(cntAddr, 0, Nv * sizeof(int));

    k_histred<<<NPART, 256>>>(ei, ea);
    k_scanred<<<1, 1024>>>(W_edge, attE);
    k_scatter<<<NPART, 256>>>(ei);
    k_gemm<<<BNv / 64, 256>>>(data, W, bias, attS, attD, out);
    k_dst<<<Nv, 64>>>(ei, ea, bias, out);

    if (out_size > OUT_MAIN) {
        int total = out_size - OUT_MAIN;
        k_tail<<<(total + 255) / 256, 256>>>(ei, out + OUT_MAIN, total);
    }
}

// round 4
// speedup vs baseline: 1.1903x; 1.0501x over previous
#include <cuda_runtime.h>

#define Bv   16
#define Nv   5000
#define Ev   160000
#define Cv   64
#define BNv  80000
#define BEv  2560000
#define ETOTv 2640000
#define OUT_MAIN 5120000   // BNv * Cv
#define NPART 625          // Ev / 256

// ---------------- scratch (static __device__, no allocs) ----------------
__device__ float g_xlS[Nv * Cv];     // xl for nodes < 5000 (message sources)
__device__ float g_aS[Nv];
__device__ float g_aD[Nv];
__device__ int   g_cnt[Nv];
__device__ int   g_off[Nv + 1];
__device__ int   g_cur[Nv];
__device__ int   g_bucket[Ev];       // edge id per CSR slot
__device__ int   g_bsrc[Ev];         // src node per CSR slot
__device__ float g_bval[Ev];         // ea[e]*c per CSR slot
__device__ float g_alphaP[Ev];       // unnormalized exp(alpha) per unique edge
__device__ float g_rdenom[Nv];
__device__ float g_selfNorm[Nv];
__device__ float g_part[NPART];
__device__ float g_c;                // sum_k W_edge[k]*att_edge[k]
__device__ float g_meanC;            // mean(edge_attr) * c

// ---------------- f32x2 packed helpers ----------------
__device__ __forceinline__ unsigned long long pk2(float lo, float hi) {
    unsigned long long u;
    asm("mov.b64 %0, {%1, %2};" : "=l"(u) : "f"(lo), "f"(hi));
    return u;
}
__device__ __forceinline__ void fma2(unsigned long long& acc, unsigned long long a, unsigned long long b) {
    asm("fma.rn.f32x2 %0, %1, %2, %3;" : "=l"(acc) : "l"(a), "l"(b), "l"(acc));
}
__device__ __forceinline__ void upk2(unsigned long long u, float& lo, float& hi) {
    asm("mov.b64 {%0, %1}, %2;" : "=f"(lo), "=f"(hi) : "l"(u));
}

// ---------------- fused histogram + edge_attr partial sums ----------------
__global__ void k_histred(const int* __restrict__ ei, const float* __restrict__ ea) {
    __shared__ float sh[256];
    int e = blockIdx.x * 256 + threadIdx.x;          // exact: Ev = 625*256
    atomicAdd(&g_cnt[ei[Ev + e]], 1);                // row 1 = dst
    sh[threadIdx.x] = ea[e];
    __syncthreads();
#pragma unroll
    for (int o = 128; o > 0; o >>= 1) {
        if (threadIdx.x < o) sh[threadIdx.x] += sh[threadIdx.x + o];
        __syncthreads();
    }
    if (threadIdx.x == 0) g_part[blockIdx.x] = sh[0];
}

// ------- fused: reduce partials + compute c + exclusive scan (shfl) -------
__global__ void k_scanred(const float* __restrict__ W_edge, const float* __restrict__ att_edge) {
    __shared__ float fred[32];
    __shared__ int   ired[32];
    int t = threadIdx.x;
    int lane = t & 31, w = t >> 5;

    // A1: sum of ea partials (625 elems over 1024 threads)
    float s = (t < NPART) ? g_part[t] : 0.f;
#pragma unroll
    for (int o = 16; o; o >>= 1) s += __shfl_xor_sync(0xffffffffu, s, o);
    if (lane == 0) fred[w] = s;

    // B: exclusive scan of g_cnt (5 per thread)
    int v[5]; int mysum = 0;
#pragma unroll
    for (int j = 0; j < 5; j++) {
        int i = t * 5 + j;
        v[j] = (i < Nv) ? g_cnt[i] : 0;
        mysum += v[j];
    }
    int inc = mysum;
#pragma unroll
    for (int o = 1; o < 32; o <<= 1) {
        int n = __shfl_up_sync(0xffffffffu, inc, o);
        if (lane >= o) inc += n;
    }
    if (lane == 31) ired[w] = inc;
    __syncthreads();

    if (w == 0) {
        // finish ea sum + compute c, meanC
        float ps = fred[lane];
#pragma unroll
        for (int o = 16; o; o >>= 1) ps += __shfl_xor_sync(0xffffffffu, ps, o);
        float cv = W_edge[lane] * att_edge[lane] + W_edge[lane + 32] * att_edge[lane + 32];
#pragma unroll
        for (int o = 16; o; o >>= 1) cv += __shfl_xor_sync(0xffffffffu, cv, o);
        if (lane == 0) { g_c = cv; g_meanC = (ps / (float)Ev) * cv; }
        // scan of warp sums
        int x = ired[lane];
#pragma unroll
        for (int o = 1; o < 32; o <<= 1) {
            int n = __shfl_up_sync(0xffffffffu, x, o);
            if (lane >= o) x += n;
        }
        ired[lane] = x;
    }
    __syncthreads();

    int base = (w > 0) ? ired[w - 1] : 0;
    int run = base + inc - mysum;   // exclusive prefix for this thread's first elem
#pragma unroll
    for (int j = 0; j < 5; j++) {
        int i = t * 5 + j;
        if (i < Nv) { g_off[i] = run; g_cur[i] = run; run += v[j]; }
    }
    if (t == 1023) g_off[Nv] = run;
}

__global__ void k_scatter(const int* __restrict__ ei, const float* __restrict__ ea) {
    int e = blockIdx.x * 256 + threadIdx.x;          // exact grid
    int d = ei[Ev + e];
    int s = ei[e];
    float val = ea[e] * g_c;
    int p = atomicAdd(&g_cur[d], 1);
    g_bucket[p] = e;
    g_bsrc[p]   = s;
    g_bval[p]   = val;
}

// ---- dense transform: xl = x @ W^T (+bias into out) + fused attn dots ----
// Block tile: 128 rows x 64 cols, 256 threads, 8x4 per thread, f32x2 FMA.
// SMEM layout: panel-of-4-k: Xs4[k4][row][kin], Ws4[k4][col][kin]. 48KB exact.
__global__ void __launch_bounds__(256) k_gemm(const float* __restrict__ x,
                                              const float* __restrict__ W,
                                              const float* __restrict__ bias,
                                              const float* __restrict__ attS,
                                              const float* __restrict__ attD,
                                              float* __restrict__ out) {
    __shared__ float Xs4[16 * 128 * 4];   // 32768 B
    __shared__ float Ws4[16 * 64 * 4];    // 16384 B
    int tid = threadIdx.x;
    int nb = blockIdx.x * 128;

    // stage X: 2048 float4, conflict-free STS.128 (row fastest across lanes)
#pragma unroll
    for (int it = 0; it < 8; it++) {
        int fl = tid + it * 256;
        int row = fl & 127, q = fl >> 7;
        float4 v = *(const float4*)(x + (long long)(nb + row) * 64 + q * 4);
        *(float4*)(Xs4 + q * 512 + row * 4) = v;
    }
    // stage W: 1024 float4
#pragma unroll
    for (int it = 0; it < 4; it++) {
        int fl = tid + it * 256;
        int col = fl & 63, q = fl >> 6;
        float4 v = *(const float4*)(W + col * 64 + q * 4);
        *(float4*)(Ws4 + q * 256 + col * 4) = v;
    }
    __syncthreads();

    int tx = tid & 15, ty = tid >> 4;
    int r0 = ty * 8, c0 = tx * 4;

    unsigned long long accp[4][4];        // [row-pair][col], packed (r even, r odd)
#pragma unroll
    for (int p = 0; p < 4; p++)
#pragma unroll
        for (int j = 0; j < 4; j++) accp[p][j] = 0ull;   // bits of (0.f,0.f)

#pragma unroll
    for (int q = 0; q < 16; q++) {
        // B columns for this k4-panel, pre-broadcast per kin
        unsigned long long bp[4][4];      // [kin][col]
#pragma unroll
        for (int j = 0; j < 4; j++) {
            float4 b = *(const float4*)(Ws4 + q * 256 + (c0 + j) * 4);
            const float* bf = (const float*)&b;
#pragma unroll
            for (int kin = 0; kin < 4; kin++) bp[kin][j] = pk2(bf[kin], bf[kin]);
        }
#pragma unroll
        for (int p = 0; p < 4; p++) {
            float4 a0 = *(const float4*)(Xs4 + q * 512 + (r0 + 2 * p) * 4);
            float4 a1 = *(const float4*)(Xs4 + q * 512 + (r0 + 2 * p + 1) * 4);
            const float* a0f = (const float*)&a0;
            const float* a1f = (const float*)&a1;
#pragma unroll
            for (int kin = 0; kin < 4; kin++) {
                unsigned long long ap = pk2(a0f[kin], a1f[kin]);
#pragma unroll
                for (int j = 0; j < 4; j++) fma2(accp[p][j], ap, bp[kin][j]);
            }
        }
    }

    // unpack accumulators: acc[i][j], i = row offset 0..7
    float acc[8][4];
#pragma unroll
    for (int p = 0; p < 4; p++)
#pragma unroll
        for (int j = 0; j < 4; j++) upk2(accp[p][j], acc[2 * p][j], acc[2 * p + 1][j]);

    float4 bb = *(const float4*)(bias + c0);
#pragma unroll
    for (int i = 0; i < 8; i++) {
        int n = nb + r0 + i;
        float4 o;
        o.x = acc[i][0] + bb.x; o.y = acc[i][1] + bb.y;
        o.z = acc[i][2] + bb.z; o.w = acc[i][3] + bb.w;
        *(float4*)(out + (long long)n * 64 + c0) = o;
        if (n < Nv) {
            float4 xo;
            xo.x = acc[i][0]; xo.y = acc[i][1]; xo.z = acc[i][2]; xo.w = acc[i][3];
            *(float4*)(&g_xlS[n * 64 + c0]) = xo;
        }
    }
    // fused attention dots for source nodes (< Nv)
    if (nb < Nv) {
        float4 as4 = *(const float4*)(attS + c0);
        float4 ad4 = *(const float4*)(attD + c0);
        float ps[8], pd[8];
#pragma unroll
        for (int i = 0; i < 8; i++) {
            ps[i] = acc[i][0] * as4.x + acc[i][1] * as4.y + acc[i][2] * as4.z + acc[i][3] * as4.w;
            pd[i] = acc[i][0] * ad4.x + acc[i][1] * ad4.y + acc[i][2] * ad4.z + acc[i][3] * ad4.w;
        }
#pragma unroll
        for (int o = 8; o > 0; o >>= 1) {
#pragma unroll
            for (int i = 0; i < 8; i++) {
                ps[i] += __shfl_xor_sync(0xffffffffu, ps[i], o);
                pd[i] += __shfl_xor_sync(0xffffffffu, pd[i], o);
            }
        }
        if (tx == 0) {
#pragma unroll
            for (int i = 0; i < 8; i++) {
                int n = nb + r0 + i;
                if (n < Nv) { g_aS[n] = ps[i]; g_aD[n] = pd[i]; }
            }
        }
    }
}

// ------- per-destination softmax + aggregation (single pass, no amax) -------
__global__ void __launch_bounds__(64) k_dst(const float* __restrict__ bias,
                                            float* __restrict__ out) {
    int d = blockIdx.x;
    int t = threadIdx.x;        // 64 threads = 64 channels
    int s0 = g_off[d], s1 = g_off[d + 1];
    float aDd = g_aD[d];
    float pSelf;
    {
        float xv = g_aS[d] + aDd + g_meanC;
        xv = xv > 0.f ? xv : 0.2f * xv;
        pSelf = __expf(xv);
    }
    __shared__ float sP[64];
    __shared__ int   sS[64];
    __shared__ float red[64];
    float acc = 0.f;
    float psum = 0.f;
    for (int base = s0; base < s1; base += 64) {
        int m = s1 - base; if (m > 64) m = 64;
        if (t < m) {
            int idx = base + t;
            int s = g_bsrc[idx];
            float xv = g_aS[s] + aDd + g_bval[idx];
            xv = xv > 0.f ? xv : 0.2f * xv;
            float p = __expf(xv);
            sP[t] = p; sS[t] = s;
            psum += p;
            g_alphaP[g_bucket[idx]] = p;
        }
        __syncthreads();
        int j = 0;
        for (; j + 4 <= m; j += 4) {
            float p0 = sP[j], p1 = sP[j + 1], p2 = sP[j + 2], p3 = sP[j + 3];
            float v0 = g_xlS[sS[j] * 64 + t];
            float v1 = g_xlS[sS[j + 1] * 64 + t];
            float v2 = g_xlS[sS[j + 2] * 64 + t];
            float v3 = g_xlS[sS[j + 3] * 64 + t];
            acc += p0 * v0; acc += p1 * v1; acc += p2 * v2; acc += p3 * v3;
        }
        for (; j < m; j++) acc += sP[j] * g_xlS[sS[j] * 64 + t];
        __syncthreads();
    }
    red[t] = psum; __syncthreads();
#pragma unroll
    for (int o = 32; o > 0; o >>= 1) {
        if (t < o) red[t] += red[t + o];
        __syncthreads();
    }
    float sumP = red[0];
    float denom = (float)Bv * sumP + pSelf;
    float rd = 1.f / (denom + 1e-16f);
    out[(long long)d * 64 + t] = ((float)Bv * acc + pSelf * g_xlS[d * 64 + t]) * rd + bias[t];
    if (t == 0) { g_rdenom[d] = rd; g_selfNorm[d] = pSelf * rd; }
}

// ------- tuple tail part 1: src/dst rows (depends only on ei) -------
__global__ void k_tail_sd(const int* __restrict__ ei, float* __restrict__ outTail) {
    int i = blockIdx.x * 256 + threadIdx.x;
    if (i >= 2 * ETOTv) return;
    float val;
    if (i < ETOTv) {
        val = (i < BEv) ? (float)ei[i - (i / Ev) * Ev] : (float)(i - BEv);
    } else {
        int k = i - ETOTv;
        val = (k < BEv) ? (float)ei[Ev + (k - (k / Ev) * Ev)] : (float)(k - BEv);
    }
    outTail[i] = val;
}

// ------- tuple tail part 2: alpha (depends on k_dst) -------
__global__ void k_tail_alpha(const int* __restrict__ ei, float* __restrict__ outA, int totalA) {
    int i = blockIdx.x * 256 + threadIdx.x;
    if (i >= totalA) return;
    float val;
    if (i < BEv) {
        int e = i - (i / Ev) * Ev;
        val = g_alphaP[e] * g_rdenom[ei[Ev + e]];
    } else if (i < BEv + BNv) {
        int d = i - BEv;
        val = (d < Nv) ? g_selfNorm[d] : 1.0f;
    } else {
        val = 0.f;
    }
    outA[i] = val;
}

// ---------------- launch ----------------
extern "C" void kernel_launch(void* const* d_in, const int* in_sizes, int n_in,
                              void* d_out, int out_size) {
    const float* data   = (const float*)d_in[0];
    const int*   ei     = (const int*)  d_in[1];
    const float* ea     = (const float*)d_in[2];
    const float* W      = (const float*)d_in[3];
    const float* W_edge = (const float*)d_in[4];
    const float* attS   = (const float*)d_in[5];
    const float* attD   = (const float*)d_in[6];
    const float* attE   = (const float*)d_in[7];
    const float* bias   = (const float*)d_in[8];
    float* out = (float*)d_out;

    static cudaStream_t sB = nullptr, sC = nullptr;
    static cudaEvent_t eFork = nullptr, eB = nullptr, eC = nullptr;
    if (!sB) {
        cudaStreamCreateWithFlags(&sB, cudaStreamNonBlocking);
        cudaStreamCreateWithFlags(&sC, cudaStreamNonBlocking);
        cudaEventCreateWithFlags(&eFork, cudaEventDisableTiming);
        cudaEventCreateWithFlags(&eB, cudaEventDisableTiming);
        cudaEventCreateWithFlags(&eC, cudaEventDisableTiming);
    }

    void* cntAddr = nullptr;
    cudaGetSymbolAddress(&cntAddr, g_cnt);

    // fork: side chain (CSR build) on sB, tail_sd on sC, GEMM on main stream
    cudaEventRecord(eFork, 0);
    cudaStreamWaitEvent(sB, eFork, 0);
    cudaStreamWaitEvent(sC, eFork, 0);

    cudaMemsetAsync(cntAddr, 0, Nv * sizeof(int), sB);
    k_histred<<<NPART, 256, 0, sB>>>(ei, ea);
    k_scanred<<<1, 1024, 0, sB>>>(W_edge, attE);
    k_scatter<<<NPART, 256, 0, sB>>>(ei, ea);
    cudaEventRecord(eB, sB);

    if (out_size > OUT_MAIN) {
        k_tail_sd<<<(2 * ETOTv + 255) / 256, 256, 0, sC>>>(ei, out + OUT_MAIN);
    }
    cudaEventRecord(eC, sC);

    k_gemm<<<BNv / 128, 256>>>(data, W, bias, attS, attD, out);

    // join, then dst softmax/aggregate, then alpha tail
    cudaStreamWaitEvent(0, eB, 0);
    cudaStreamWaitEvent(0, eC, 0);
    k_dst<<<Nv, 64>>>(bias, out);

    if (out_size > OUT_MAIN) {
        int totalA = out_size - OUT_MAIN - 2 * ETOTv;
        if (totalA > 0)
            k_tail_alpha<<<(totalA + 255) / 256, 256>>>(ei, out + OUT_MAIN + 2 * ETOTv, totalA);
    }
}

// round 5
// speedup vs baseline: 1.3880x; 1.1661x over previous
#include <cuda_runtime.h>

#define Bv   16
#define Nv   5000
#define Ev   160000
#define Cv   64
#define BNv  80000
#define BEv  2560000
#define ETOTv 2640000
#define OUT_MAIN 5120000   // BNv * Cv
#define NPART 625          // Ev / 256

// ---------------- scratch (static __device__, no allocs) ----------------
__device__ float g_xlS[Nv * Cv];     // xl for nodes < 5000 (message sources)
__device__ float g_aS[Nv];
__device__ float g_aD[Nv];
__device__ int   g_cnt[Nv];
__device__ int   g_off[Nv + 1];
__device__ int   g_cur[Nv];
__device__ int   g_bucket[Ev];       // edge id per CSR slot
__device__ int   g_bsrc[Ev];         // src node per CSR slot
__device__ float g_bval[Ev];         // ea[e]*c per CSR slot
__device__ float g_alphaP[Ev];       // NORMALIZED alpha per unique edge (after k_dst)
__device__ float g_selfNorm[Nv];
__device__ float g_part[NPART];
__device__ float g_c;                // sum_k W_edge[k]*att_edge[k]
__device__ float g_meanC;            // mean(edge_attr) * c

// ---------------- f32x2 packed helpers ----------------
__device__ __forceinline__ unsigned long long pk2(float lo, float hi) {
    unsigned long long u;
    asm("mov.b64 %0, {%1, %2};" : "=l"(u) : "f"(lo), "f"(hi));
    return u;
}
__device__ __forceinline__ void fma2(unsigned long long& acc, unsigned long long a, unsigned long long b) {
    asm("fma.rn.f32x2 %0, %1, %2, %3;" : "=l"(acc) : "l"(a), "l"(b), "l"(acc));
}
__device__ __forceinline__ void upk2(unsigned long long u, float& lo, float& hi) {
    asm("mov.b64 {%0, %1}, %2;" : "=f"(lo), "=f"(hi) : "l"(u));
}

// ---------------- fused histogram + edge_attr partial sums ----------------
__global__ void k_histred(const int* __restrict__ ei, const float* __restrict__ ea) {
    int e = blockIdx.x * 256 + threadIdx.x;          // exact: Ev = 625*256
    atomicAdd(&g_cnt[ei[Ev + e]], 1);                // row 1 = dst
    float s = ea[e];
#pragma unroll
    for (int o = 16; o; o >>= 1) s += __shfl_xor_sync(0xffffffffu, s, o);
    __shared__ float sh[8];
    if ((threadIdx.x & 31) == 0) sh[threadIdx.x >> 5] = s;
    __syncthreads();
    if (threadIdx.x < 8) {
        float v = sh[threadIdx.x];
#pragma unroll
        for (int o = 4; o; o >>= 1) v += __shfl_xor_sync(0xffu, v, o);
        if (threadIdx.x == 0) g_part[blockIdx.x] = v;
    }
}

// ------- fused: reduce partials + compute c + exclusive scan (shfl) -------
__global__ void k_scanred(const float* __restrict__ W_edge, const float* __restrict__ att_edge) {
    __shared__ float fred[32];
    __shared__ int   ired[32];
    int t = threadIdx.x;
    int lane = t & 31, w = t >> 5;

    float s = (t < NPART) ? g_part[t] : 0.f;
#pragma unroll
    for (int o = 16; o; o >>= 1) s += __shfl_xor_sync(0xffffffffu, s, o);
    if (lane == 0) fred[w] = s;

    int v[5]; int mysum = 0;
#pragma unroll
    for (int j = 0; j < 5; j++) {
        int i = t * 5 + j;
        v[j] = (i < Nv) ? g_cnt[i] : 0;
        mysum += v[j];
    }
    int inc = mysum;
#pragma unroll
    for (int o = 1; o < 32; o <<= 1) {
        int n = __shfl_up_sync(0xffffffffu, inc, o);
        if (lane >= o) inc += n;
    }
    if (lane == 31) ired[w] = inc;
    __syncthreads();

    if (w == 0) {
        float ps = fred[lane];
#pragma unroll
        for (int o = 16; o; o >>= 1) ps += __shfl_xor_sync(0xffffffffu, ps, o);
        float cv = W_edge[lane] * att_edge[lane] + W_edge[lane + 32] * att_edge[lane + 32];
#pragma unroll
        for (int o = 16; o; o >>= 1) cv += __shfl_xor_sync(0xffffffffu, cv, o);
        if (lane == 0) { g_c = cv; g_meanC = (ps / (float)Ev) * cv; }
        int x = ired[lane];
#pragma unroll
        for (int o = 1; o < 32; o <<= 1) {
            int n = __shfl_up_sync(0xffffffffu, x, o);
            if (lane >= o) x += n;
        }
        ired[lane] = x;
    }
    __syncthreads();

    int base = (w > 0) ? ired[w - 1] : 0;
    int run = base + inc - mysum;
#pragma unroll
    for (int j = 0; j < 5; j++) {
        int i = t * 5 + j;
        if (i < Nv) { g_off[i] = run; g_cur[i] = run; run += v[j]; }
    }
    if (t == 1023) g_off[Nv] = run;
}

__global__ void k_scatter(const int* __restrict__ ei, const float* __restrict__ ea) {
    int e = blockIdx.x * 256 + threadIdx.x;          // exact grid
    int d = ei[Ev + e];
    int s = ei[e];
    float val = ea[e] * g_c;
    int p = atomicAdd(&g_cur[d], 1);
    g_bucket[p] = e;
    g_bsrc[p]   = s;
    g_bval[p]   = val;
}

// ---- dense transform: xl = x @ W^T (+bias into out) + fused attn dots ----
__global__ void __launch_bounds__(256) k_gemm(const float* __restrict__ x,
                                              const float* __restrict__ W,
                                              const float* __restrict__ bias,
                                              const float* __restrict__ attS,
                                              const float* __restrict__ attD,
                                              float* __restrict__ out) {
    __shared__ float Xs4[16 * 128 * 4];   // 32768 B
    __shared__ float Ws4[16 * 64 * 4];    // 16384 B
    int tid = threadIdx.x;
    int nb = blockIdx.x * 128;

#pragma unroll
    for (int it = 0; it < 8; it++) {
        int fl = tid + it * 256;
        int row = fl & 127, q = fl >> 7;
        float4 v = *(const float4*)(x + (long long)(nb + row) * 64 + q * 4);
        *(float4*)(Xs4 + q * 512 + row * 4) = v;
    }
#pragma unroll
    for (int it = 0; it < 4; it++) {
        int fl = tid + it * 256;
        int col = fl & 63, q = fl >> 6;
        float4 v = *(const float4*)(W + col * 64 + q * 4);
        *(float4*)(Ws4 + q * 256 + col * 4) = v;
    }
    __syncthreads();

    int tx = tid & 15, ty = tid >> 4;
    int r0 = ty * 8, c0 = tx * 4;

    unsigned long long accp[4][4];
#pragma unroll
    for (int p = 0; p < 4; p++)
#pragma unroll
        for (int j = 0; j < 4; j++) accp[p][j] = 0ull;

#pragma unroll
    for (int q = 0; q < 16; q++) {
        unsigned long long bp[4][4];
#pragma unroll
        for (int j = 0; j < 4; j++) {
            float4 b = *(const float4*)(Ws4 + q * 256 + (c0 + j) * 4);
            const float* bf = (const float*)&b;
#pragma unroll
            for (int kin = 0; kin < 4; kin++) bp[kin][j] = pk2(bf[kin], bf[kin]);
        }
#pragma unroll
        for (int p = 0; p < 4; p++) {
            float4 a0 = *(const float4*)(Xs4 + q * 512 + (r0 + 2 * p) * 4);
            float4 a1 = *(const float4*)(Xs4 + q * 512 + (r0 + 2 * p + 1) * 4);
            const float* a0f = (const float*)&a0;
            const float* a1f = (const float*)&a1;
#pragma unroll
            for (int kin = 0; kin < 4; kin++) {
                unsigned long long ap = pk2(a0f[kin], a1f[kin]);
#pragma unroll
                for (int j = 0; j < 4; j++) fma2(accp[p][j], ap, bp[kin][j]);
            }
        }
    }

    float acc[8][4];
#pragma unroll
    for (int p = 0; p < 4; p++)
#pragma unroll
        for (int j = 0; j < 4; j++) upk2(accp[p][j], acc[2 * p][j], acc[2 * p + 1][j]);

    float4 bb = *(const float4*)(bias + c0);
#pragma unroll
    for (int i = 0; i < 8; i++) {
        int n = nb + r0 + i;
        float4 o;
        o.x = acc[i][0] + bb.x; o.y = acc[i][1] + bb.y;
        o.z = acc[i][2] + bb.z; o.w = acc[i][3] + bb.w;
        *(float4*)(out + (long long)n * 64 + c0) = o;
        if (n < Nv) {
            float4 xo;
            xo.x = acc[i][0]; xo.y = acc[i][1]; xo.z = acc[i][2]; xo.w = acc[i][3];
            *(float4*)(&g_xlS[n * 64 + c0]) = xo;
        }
    }
    if (nb < Nv) {
        float4 as4 = *(const float4*)(attS + c0);
        float4 ad4 = *(const float4*)(attD + c0);
        float ps[8], pd[8];
#pragma unroll
        for (int i = 0; i < 8; i++) {
            ps[i] = acc[i][0] * as4.x + acc[i][1] * as4.y + acc[i][2] * as4.z + acc[i][3] * as4.w;
            pd[i] = acc[i][0] * ad4.x + acc[i][1] * ad4.y + acc[i][2] * ad4.z + acc[i][3] * ad4.w;
        }
#pragma unroll
        for (int o = 8; o > 0; o >>= 1) {
#pragma unroll
            for (int i = 0; i < 8; i++) {
                ps[i] += __shfl_xor_sync(0xffffffffu, ps[i], o);
                pd[i] += __shfl_xor_sync(0xffffffffu, pd[i], o);
            }
        }
        if (tx == 0) {
#pragma unroll
            for (int i = 0; i < 8; i++) {
                int n = nb + r0 + i;
                if (n < Nv) { g_aS[n] = ps[i]; g_aD[n] = pd[i]; }
            }
        }
    }
}

// ------- per-destination softmax + aggregation: ONE WARP PER DST -------
__global__ void __launch_bounds__(256) k_dst(const float* __restrict__ bias,
                                             float* __restrict__ out) {
    int wIdx = threadIdx.x >> 5;                 // warp within block (0..7)
    int d = blockIdx.x * 8 + wIdx;               // destination node
    int lane = threadIdx.x & 31;
    if (d >= Nv) return;
    int s0 = g_off[d], s1 = g_off[d + 1];
    float aDd = g_aD[d];
    float pSelf;
    {
        float xv = g_aS[d] + aDd + g_meanC;
        xv = xv > 0.f ? xv : 0.2f * xv;
        pSelf = __expf(xv);
    }
    __shared__ float sP[8][32];
    __shared__ int   sS[8][32];
    float accx = 0.f, accy = 0.f, accx1 = 0.f, accy1 = 0.f;
    float psum = 0.f;
    for (int base = s0; base < s1; base += 32) {
        int m = s1 - base; if (m > 32) m = 32;
        float p = 0.f;
        if (lane < m) {
            int idx = base + lane;
            int s = g_bsrc[idx];
            float xv = g_aS[s] + aDd + g_bval[idx];
            xv = xv > 0.f ? xv : 0.2f * xv;
            p = __expf(xv);
            psum += p;
            sP[wIdx][lane] = p;
            sS[wIdx][lane] = s;
        }
        __syncwarp();
        int j = 0;
        for (; j + 2 <= m; j += 2) {
            float p0 = sP[wIdx][j],     p1 = sP[wIdx][j + 1];
            int   q0 = sS[wIdx][j],     q1 = sS[wIdx][j + 1];
            float2 v0 = *(const float2*)(g_xlS + q0 * 64 + lane * 2);
            float2 v1 = *(const float2*)(g_xlS + q1 * 64 + lane * 2);
            accx  += p0 * v0.x; accy  += p0 * v0.y;
            accx1 += p1 * v1.x; accy1 += p1 * v1.y;
        }
        if (j < m) {
            float p0 = sP[wIdx][j];
            int   q0 = sS[wIdx][j];
            float2 v0 = *(const float2*)(g_xlS + q0 * 64 + lane * 2);
            accx += p0 * v0.x; accy += p0 * v0.y;
        }
        __syncwarp();
    }
    accx += accx1; accy += accy1;
#pragma unroll
    for (int o = 16; o; o >>= 1) psum += __shfl_xor_sync(0xffffffffu, psum, o);
    float denom = (float)Bv * psum + pSelf;
    float rd = 1.f / (denom + 1e-16f);
    float2 xs = *(const float2*)(g_xlS + d * 64 + lane * 2);
    float2 bb = *(const float2*)(bias + lane * 2);
    float2 o2;
    o2.x = ((float)Bv * accx + pSelf * xs.x) * rd + bb.x;
    o2.y = ((float)Bv * accy + pSelf * xs.y) * rd + bb.y;
    *(float2*)(out + (long long)d * 64 + lane * 2) = o2;
    if (lane == 0) g_selfNorm[d] = pSelf * rd;
    // write NORMALIZED alpha per unique edge
    for (int idx = s0 + lane; idx < s1; idx += 32) {
        g_alphaP[g_bucket[idx]] = sP[wIdx][0] * 0.f +   // keep smem live? no — recompute below
                                  0.f;
    }
    // NOTE: sP only holds the last chunk; recompute p for the normalized store.
    for (int idx = s0 + lane; idx < s1; idx += 32) {
        int s = g_bsrc[idx];
        float xv = g_aS[s] + aDd + g_bval[idx];
        xv = xv > 0.f ? xv : 0.2f * xv;
        g_alphaP[g_bucket[idx]] = __expf(xv) * rd;
    }
}

// ------- tuple tail part 1: src/dst rows, float4 (depends only on ei) -------
__global__ void k_tail_sd(const int* __restrict__ ei, float* __restrict__ outTail) {
    int i = (blockIdx.x * 256 + threadIdx.x) * 4;
    if (i >= 2 * ETOTv) return;
    float4 v;
    if (i < ETOTv) {
        if (i < BEv) {
            int e = i - (i / Ev) * Ev;
            v.x = (float)ei[e]; v.y = (float)ei[e + 1];
            v.z = (float)ei[e + 2]; v.w = (float)ei[e + 3];
        } else {
            float b0 = (float)(i - BEv);
            v.x = b0; v.y = b0 + 1.f; v.z = b0 + 2.f; v.w = b0 + 3.f;
        }
    } else {
        int k = i - ETOTv;
        if (k < BEv) {
            int e = k - (k / Ev) * Ev;
            v.x = (float)ei[Ev + e]; v.y = (float)ei[Ev + e + 1];
            v.z = (float)ei[Ev + e + 2]; v.w = (float)ei[Ev + e + 3];
        } else {
            float b0 = (float)(k - BEv);
            v.x = b0; v.y = b0 + 1.f; v.z = b0 + 2.f; v.w = b0 + 3.f;
        }
    }
    *(float4*)(outTail + i) = v;
}

// ------- tuple tail part 2: alpha, float4 (depends on k_dst) -------
__global__ void k_tail_alpha(float* __restrict__ outA, int totalA) {
    int i = (blockIdx.x * 256 + threadIdx.x) * 4;
    if (i >= totalA) return;
    float4 v;
    if (i < BEv) {
        int e = i - (i / Ev) * Ev;
        v = *(const float4*)(g_alphaP + e);
    } else {
        int d = i - BEv;
        if (d + 3 < Nv) {
            v.x = g_selfNorm[d]; v.y = g_selfNorm[d + 1];
            v.z = g_selfNorm[d + 2]; v.w = g_selfNorm[d + 3];
        } else {
            v.x = (d     < Nv) ? g_selfNorm[d]     : 1.0f;
            v.y = (d + 1 < Nv) ? g_selfNorm[d + 1] : 1.0f;
            v.z = (d + 2 < Nv) ? g_selfNorm[d + 2] : 1.0f;
            v.w = (d + 3 < Nv) ? g_selfNorm[d + 3] : 1.0f;
        }
    }
    *(float4*)(outA + i) = v;
}

// ---------------- launch ----------------
extern "C" void kernel_launch(void* const* d_in, const int* in_sizes, int n_in,
                              void* d_out, int out_size) {
    const float* data   = (const float*)d_in[0];
    const int*   ei     = (const int*)  d_in[1];
    const float* ea     = (const float*)d_in[2];
    const float* W      = (const float*)d_in[3];
    const float* W_edge = (const float*)d_in[4];
    const float* attS   = (const float*)d_in[5];
    const float* attD   = (const float*)d_in[6];
    const float* attE   = (const float*)d_in[7];
    const float* bias   = (const float*)d_in[8];
    float* out = (float*)d_out;

    static cudaStream_t sB = nullptr, sC = nullptr;
    static cudaEvent_t eFork = nullptr, eB = nullptr, eC = nullptr;
    if (!sB) {
        cudaStreamCreateWithFlags(&sB, cudaStreamNonBlocking);
        cudaStreamCreateWithFlags(&sC, cudaStreamNonBlocking);
        cudaEventCreateWithFlags(&eFork, cudaEventDisableTiming);
        cudaEventCreateWithFlags(&eB, cudaEventDisableTiming);
        cudaEventCreateWithFlags(&eC, cudaEventDisableTiming);
    }

    void* cntAddr = nullptr;
    cudaGetSymbolAddress(&cntAddr, g_cnt);

    cudaEventRecord(eFork, 0);
    cudaStreamWaitEvent(sB, eFork, 0);
    cudaStreamWaitEvent(sC, eFork, 0);

    cudaMemsetAsync(cntAddr, 0, Nv * sizeof(int), sB);
    k_histred<<<NPART, 256, 0, sB>>>(ei, ea);
    k_scanred<<<1, 1024, 0, sB>>>(W_edge, attE);
    k_scatter<<<NPART, 256, 0, sB>>>(ei, ea);
    cudaEventRecord(eB, sB);

    if (out_size > OUT_MAIN) {
        int n4 = (2 * ETOTv) / 4;
        k_tail_sd<<<(n4 + 255) / 256, 256, 0, sC>>>(ei, out + OUT_MAIN);
    }
    cudaEventRecord(eC, sC);

    k_gemm<<<BNv / 128, 256>>>(data, W, bias, attS, attD, out);

    cudaStreamWaitEvent(0, eB, 0);
    cudaStreamWaitEvent(0, eC, 0);
    k_dst<<<(Nv + 7) / 8, 256>>>(bias, out);

    if (out_size > OUT_MAIN) {
        int totalA = out_size - OUT_MAIN - 2 * ETOTv;
        if (totalA > 0) {
            int n4 = (totalA + 3) / 4;
            k_tail_alpha<<<(n4 + 255) / 256, 256>>>(out + OUT_MAIN + 2 * ETOTv, totalA);
        }
    }
}